// round 1
// baseline (speedup 1.0000x reference)
#include <cuda_runtime.h>

// Problem constants
#define BB 2048
#define LL 256
#define FF 64
#define HH 32
#define G4 256   // 4*F

// Scratch (device globals; no allocation allowed)
__device__ float d_A[BB * G4];     // per-batch input bias: (b_emb+g_vec[b])@Wi + b_lstm
__device__ float d_E[2 * G4];      // per-token embedding projection: W_emb[k]@Wi
__device__ float d_h0[BB * FF];
__device__ float d_c0[BB * FF];

typedef unsigned long long u64;

__device__ __forceinline__ u64 pack2(float lo, float hi) {
    u64 r; asm("mov.b64 %0, {%1,%2};" : "=l"(r) : "f"(lo), "f"(hi)); return r;
}
__device__ __forceinline__ void fma2(u64 &d, u64 a, u64 b) {
    // packed 2xf32 FMA (Blackwell): d.lo += a.lo*b.lo ; d.hi += a.hi*b.hi
    asm("fma.rn.f32x2 %0, %1, %2, %0;" : "+l"(d) : "l"(a), "l"(b));
}
__device__ __forceinline__ float sum2(u64 v) {
    float lo, hi; asm("mov.b64 {%0,%1}, %2;" : "=f"(lo), "=f"(hi) : "l"(v));
    return lo + hi;
}

__device__ __forceinline__ float sigf(float x) {
    return __fdividef(1.f, 1.f + __expf(-x));
}
__device__ __forceinline__ float tanh_fast(float x) {
    return __fdividef(2.f, 1.f + __expf(-2.f * x)) - 1.f;
}

// ---------------------------------------------------------------------------
// Kernel 1: precompute A[b], E[k], h0[b], c0[b]
// grid = B, block = 256
// ---------------------------------------------------------------------------
__global__ void precompute_kernel(
    const float* __restrict__ g,
    const float* __restrict__ W_emb,  // (2,64)
    const float* __restrict__ b_emb,  // (64)
    const float* __restrict__ W_g1,   // (1,32)
    const float* __restrict__ b_g1,   // (32)
    const float* __restrict__ W_g2,   // (32,64)
    const float* __restrict__ b_g2,   // (64)
    const float* __restrict__ W_gh,   // (1,64)
    const float* __restrict__ b_gh,   // (64)
    const float* __restrict__ W_gc,   // (1,64)
    const float* __restrict__ b_gc,   // (64)
    const float* __restrict__ Wi,     // (64,256)
    const float* __restrict__ b_lstm) // (256)
{
    int b = blockIdx.x;
    int j = threadIdx.x;
    __shared__ float sh_t[HH];
    __shared__ float sh_gv[FF];

    float gb = g[b];
    if (j < HH) sh_t[j] = tanhf(gb * W_g1[j] + b_g1[j]);
    __syncthreads();
    if (j < FF) {
        float acc = b_g2[j];
        #pragma unroll 8
        for (int h = 0; h < HH; h++) acc += sh_t[h] * W_g2[h * FF + j];
        sh_gv[j] = acc;
        d_h0[b * FF + j] = gb * W_gh[j] + b_gh[j];
        d_c0[b * FF + j] = gb * W_gc[j] + b_gc[j];
    }
    __syncthreads();
    float acc = b_lstm[j];
    #pragma unroll 8
    for (int f = 0; f < FF; f++) acc += (b_emb[f] + sh_gv[f]) * Wi[f * G4 + j];
    d_A[b * G4 + j] = acc;

    if (b == 0) {
        float e0 = 0.f, e1 = 0.f;
        #pragma unroll 8
        for (int f = 0; f < FF; f++) {
            float wi = Wi[f * G4 + j];
            e0 += W_emb[f] * wi;        // W_emb row 0
            e1 += W_emb[FF + f] * wi;   // W_emb row 1
        }
        d_E[j] = e0;
        d_E[G4 + j] = e1;
    }
}

// ---------------------------------------------------------------------------
// Kernel 2: persistent per-batch LSTM recurrence + log-softmax epilogue.
// grid = B, block = 256 (thread j owns gate column j; Wh column in registers)
// ---------------------------------------------------------------------------
__global__ void __launch_bounds__(256, 2) lstm_kernel(
    const int*   __restrict__ s,      // (B, L) int32
    const float* __restrict__ Wh,     // (64, 256)
    const float* __restrict__ W_amp,  // (64, 2)
    const float* __restrict__ b_amp,  // (2)
    float* __restrict__ out)          // (B,)
{
    int b = blockIdx.x;
    int j = threadIdx.x;

    __shared__ float sh_h[FF];
    __shared__ float sh_z[G4];
    __shared__ int   sh_tok[LL];
    __shared__ float sh_red[4];

    // Wh column j, packed as 32 x f32x2 (rows 2i, 2i+1)
    u64 w2[32];
    #pragma unroll
    for (int i = 0; i < 32; i++)
        w2[i] = pack2(Wh[(2 * i) * G4 + j], Wh[(2 * i + 1) * G4 + j]);

    float xE0 = d_E[j];
    float xE1 = d_E[G4 + j];
    float xbase  = d_A[b * G4 + j] + xE0;
    float xdelta = xE1 - xE0;

    sh_tok[j] = s[b * LL + j];
    if (j < FF) sh_h[j] = d_h0[b * FF + j];
    float c   = (j < FF) ? d_c0[b * FF + j] : 0.f;
    float wa0 = (j < FF) ? W_amp[j * 2 + 0] : 0.f;
    float wa1 = (j < FF) ? W_amp[j * 2 + 1] : 0.f;
    float ba0 = b_amp[0], ba1 = b_amp[1];
    float lpsum = 0.f;  // accumulated by thread 0 only
    __syncthreads();

    #pragma unroll 1
    for (int t = 0; t < LL + 1; t++) {
        // thread 0: fold in the previous step's logits (pipelined 1 step late)
        if (j == 0 && t > 0) {
            float l0 = sh_red[0] + sh_red[2] + ba0;
            float l1 = sh_red[1] + sh_red[3] + ba1;
            int tok = sh_tok[t - 1];
            float m = fmaxf(l0, l1);
            float lse = m + __logf(__expf(l0 - m) + __expf(l1 - m));
            lpsum += (tok ? l1 : l0) - lse;
        }

        int tok_in = (t == 0) ? 0 : sh_tok[t - 1];
        float x = xbase + (tok_in ? xdelta : 0.f);

        // z_j = x + dot(h, Wh[:, j])  via packed f32x2 FMAs, 4 accumulators
        u64 acc0 = pack2(x, 0.f), acc1 = pack2(0.f, 0.f);
        u64 acc2 = pack2(0.f, 0.f), acc3 = pack2(0.f, 0.f);
        const float4* h4p = (const float4*)sh_h;
        #pragma unroll
        for (int i = 0; i < 8; i++) {
            float4 ha = h4p[2 * i];
            float4 hb = h4p[2 * i + 1];
            fma2(acc0, pack2(ha.x, ha.y), w2[4 * i + 0]);
            fma2(acc1, pack2(ha.z, ha.w), w2[4 * i + 1]);
            fma2(acc2, pack2(hb.x, hb.y), w2[4 * i + 2]);
            fma2(acc3, pack2(hb.z, hb.w), w2[4 * i + 3]);
        }
        sh_z[j] = sum2(acc0) + sum2(acc1) + sum2(acc2) + sum2(acc3);
        __syncthreads();

        if (j < FF) {
            float zi = sh_z[j];
            float zf = sh_z[FF + j];
            float zg = sh_z[2 * FF + j];
            float zo = sh_z[3 * FF + j];
            c = sigf(zf) * c + sigf(zi) * tanh_fast(zg);
            float h = sigf(zo) * tanh_fast(c);
            sh_h[j] = h;
            if (t < LL) {
                float p0 = h * wa0;
                float p1 = h * wa1;
                #pragma unroll
                for (int o = 16; o > 0; o >>= 1) {
                    p0 += __shfl_down_sync(0xffffffffu, p0, o);
                    p1 += __shfl_down_sync(0xffffffffu, p1, o);
                }
                if ((j & 31) == 0) {
                    sh_red[(j >> 5) * 2 + 0] = p0;
                    sh_red[(j >> 5) * 2 + 1] = p1;
                }
            }
        }
        __syncthreads();
    }

    if (j == 0) out[b] = lpsum;
}

// ---------------------------------------------------------------------------
// Launch. Input order (reference signature order):
// 0:s 1:g 2:W_emb 3:b_emb 4:W_g1 5:b_g1 6:W_g2 7:b_g2 8:W_gh 9:b_gh
// 10:W_gc 11:b_gc 12:Wi 13:Wh 14:b_lstm 15:W_amp 16:b_amp
// ---------------------------------------------------------------------------
extern "C" void kernel_launch(void* const* d_in, const int* in_sizes, int n_in,
                              void* d_out, int out_size) {
    const int*   s      = (const int*)  d_in[0];
    const float* g      = (const float*)d_in[1];
    const float* W_emb  = (const float*)d_in[2];
    const float* b_emb  = (const float*)d_in[3];
    const float* W_g1   = (const float*)d_in[4];
    const float* b_g1   = (const float*)d_in[5];
    const float* W_g2   = (const float*)d_in[6];
    const float* b_g2   = (const float*)d_in[7];
    const float* W_gh   = (const float*)d_in[8];
    const float* b_gh   = (const float*)d_in[9];
    const float* W_gc   = (const float*)d_in[10];
    const float* b_gc   = (const float*)d_in[11];
    const float* Wi     = (const float*)d_in[12];
    const float* Wh     = (const float*)d_in[13];
    const float* b_lstm = (const float*)d_in[14];
    const float* W_amp  = (const float*)d_in[15];
    const float* b_amp  = (const float*)d_in[16];
    float* out = (float*)d_out;

    precompute_kernel<<<BB, 256>>>(g, W_emb, b_emb, W_g1, b_g1, W_g2, b_g2,
                                   W_gh, b_gh, W_gc, b_gc, Wi, b_lstm);
    lstm_kernel<<<BB, 256>>>(s, Wh, W_amp, b_amp, out);
}

// round 5
// speedup vs baseline: 1.0314x; 1.0314x over previous
#include <cuda_runtime.h>

#define BB 2048
#define LL 256
#define FF 64
#define HH 32
#define G4 256   // 4*F

// Scratch (device globals; no allocation allowed)
__device__ float d_A[BB * G4];     // per-batch input bias: (b_emb+g_vec[b])@Wi + b_lstm
__device__ float d_E[2 * G4];      // per-token embedding projection: W_emb[k]@Wi
__device__ float d_h0[BB * FF];
__device__ float d_c0[BB * FF];

typedef unsigned long long u64;

__device__ __forceinline__ u64 pack2(float lo, float hi) {
    u64 r; asm("mov.b64 %0, {%1,%2};" : "=l"(r) : "f"(lo), "f"(hi)); return r;
}
__device__ __forceinline__ void fma2(u64 &d, u64 a, u64 b) {
    asm("fma.rn.f32x2 %0, %1, %2, %0;" : "+l"(d) : "l"(a), "l"(b));
}
__device__ __forceinline__ u64 add2(u64 a, u64 b) {
    u64 r; asm("add.rn.f32x2 %0, %1, %2;" : "=l"(r) : "l"(a), "l"(b)); return r;
}
__device__ __forceinline__ float sum2(u64 v) {
    float lo, hi; asm("mov.b64 {%0,%1}, %2;" : "=f"(lo), "=f"(hi) : "l"(v));
    return lo + hi;
}
// Fast gates validated at rel_err 2.5e-7 in R1
__device__ __forceinline__ float sigf(float x) {
    return __fdividef(1.f, 1.f + __expf(-x));
}
__device__ __forceinline__ float tanh_fast(float x) {
    return __fdividef(2.f, 1.f + __expf(-2.f * x)) - 1.f;
}

// ---------------------------------------------------------------------------
// Kernel 1: precompute A[b], E[k], h0[b], c0[b]   (proven)
// ---------------------------------------------------------------------------
__global__ void precompute_kernel(
    const float* __restrict__ g,
    const float* __restrict__ W_emb,  const float* __restrict__ b_emb,
    const float* __restrict__ W_g1,   const float* __restrict__ b_g1,
    const float* __restrict__ W_g2,   const float* __restrict__ b_g2,
    const float* __restrict__ W_gh,   const float* __restrict__ b_gh,
    const float* __restrict__ W_gc,   const float* __restrict__ b_gc,
    const float* __restrict__ Wi,     const float* __restrict__ b_lstm)
{
    int b = blockIdx.x;
    int j = threadIdx.x;
    __shared__ float sh_t[HH];
    __shared__ float sh_gv[FF];

    float gb = g[b];
    if (j < HH) sh_t[j] = tanhf(gb * W_g1[j] + b_g1[j]);
    __syncthreads();
    if (j < FF) {
        float acc = b_g2[j];
        #pragma unroll 8
        for (int h = 0; h < HH; h++) acc += sh_t[h] * W_g2[h * FF + j];
        sh_gv[j] = acc;
        d_h0[b * FF + j] = gb * W_gh[j] + b_gh[j];
        d_c0[b * FF + j] = gb * W_gc[j] + b_gc[j];
    }
    __syncthreads();
    float acc = b_lstm[j];
    #pragma unroll 8
    for (int f = 0; f < FF; f++) acc += (b_emb[f] + sh_gv[f]) * Wi[f * G4 + j];
    d_A[b * G4 + j] = acc;

    if (b == 0) {
        float e0 = 0.f, e1 = 0.f;
        #pragma unroll 8
        for (int f = 0; f < FF; f++) {
            float wi = Wi[f * G4 + j];
            e0 += W_emb[f] * wi;
            e1 += W_emb[FF + f] * wi;
        }
        d_E[j] = e0;
        d_E[G4 + j] = e1;
    }
}

// ---------------------------------------------------------------------------
// Kernel 2: LSTM recurrence, single barrier per step.
// Thread tid -> gate column col = (tid&3)*64 + tid/4 so the 4 gate columns of
// feature g = tid/4 live in one 4-lane group. Each lane activates ITS OWN
// gate pre-activation, then activated values are shuffled. c in registers;
// h double-buffered in SMEM; logit reduction deferred one step (overlaps the
// next matvec); thread 0 consumes it two steps late.
// MATVEC COVERS ALL 64 h VALUES: i=0..7, h2[0..15], w2[0..31].
// ---------------------------------------------------------------------------
__global__ void __launch_bounds__(256, 2) lstm_kernel(
    const int*   __restrict__ s,      // (B, L)
    const float* __restrict__ Wh,     // (64, 256)
    const float* __restrict__ W_amp,  // (64, 2)
    const float* __restrict__ b_amp,  // (2)
    float* __restrict__ out)          // (B,)
{
    int b    = blockIdx.x;
    int tid  = threadIdx.x;
    int g    = tid >> 2;        // feature 0..63
    int q    = tid & 3;         // gate 0..3 (i,f,g,o)
    int col  = q * FF + g;      // gate column in [0,256)
    int lane = tid & 31;
    int warp = tid >> 5;

    __shared__ __align__(16) float sh_h[2][FF];
    __shared__ int   sh_tok[LL];
    __shared__ float sh_red[2][16];

    // Wh column `col`, rows packed as f32x2: w2[k] = (Wh[2k][col], Wh[2k+1][col])
    u64 w2[32];
    #pragma unroll
    for (int k = 0; k < 32; k++)
        w2[k] = pack2(Wh[(2 * k) * G4 + col], Wh[(2 * k + 1) * G4 + col]);

    float e0 = d_E[col];
    float xbase  = d_A[b * G4 + col] + e0;
    float xdelta = d_E[G4 + col] - e0;

    sh_tok[tid] = s[b * LL + tid];
    if (tid < FF) sh_h[0][tid] = d_h0[b * FF + tid];
    float c   = d_c0[b * FF + g];          // replicated across the 4-lane group
    float wa0 = W_amp[g * 2 + 0];
    float wa1 = W_amp[g * 2 + 1];
    float ba0 = b_amp[0], ba1 = b_amp[1];
    float lpsum = 0.f;
    float hprev = 0.f;
    __syncthreads();

    #pragma unroll 1
    for (int u = 0; u <= LL; u++) {
        int p = u & 1;

        // thread 0: consume logit for token (u-2) (written at step u-1)
        if (tid == 0 && u >= 2) {
            float l0 = ba0, l1 = ba1;
            #pragma unroll
            for (int w = 0; w < 8; w++) {
                l0 += sh_red[p][2 * w];
                l1 += sh_red[p][2 * w + 1];
            }
            int tok = sh_tok[u - 2];
            float m = fmaxf(l0, l1);
            float lse = m + __logf(__expf(l0 - m) + __expf(l1 - m));
            lpsum += (tok ? l1 : l0) - lse;
        }

        // matvec: z_col = x + dot(h[0..63], Wh[:,col]) via f32x2, 4 accumulators
        int tok_in = (u == 0) ? 0 : sh_tok[u - 1];
        float x = tok_in ? (xbase + xdelta) : xbase;
        const ulonglong2* h2 = (const ulonglong2*)sh_h[p];
        u64 a0 = pack2(x, 0.f), a1 = 0ull, a2 = 0ull, a3 = 0ull;
        #pragma unroll
        for (int i = 0; i < 8; i++) {               // FULL 64 terms
            ulonglong2 ha = h2[2 * i];              // floats 8i .. 8i+3
            ulonglong2 hb = h2[2 * i + 1];          // floats 8i+4 .. 8i+7
            fma2(a0, ha.x, w2[4 * i + 0]);
            fma2(a1, ha.y, w2[4 * i + 1]);
            fma2(a2, hb.x, w2[4 * i + 2]);
            fma2(a3, hb.y, w2[4 * i + 3]);
        }
        float z = sum2(add2(add2(a0, a1), add2(a2, a3)));

        // deferred logit partial for h(u-1): independent work overlapping the
        // matvec's dependency stalls. Sums one copy per feature (q=0 lanes).
        if (u >= 1) {
            float p0 = hprev * wa0, p1 = hprev * wa1;
            p0 += __shfl_down_sync(0xffffffffu, p0, 16);
            p1 += __shfl_down_sync(0xffffffffu, p1, 16);
            p0 += __shfl_down_sync(0xffffffffu, p0, 8);
            p1 += __shfl_down_sync(0xffffffffu, p1, 8);
            p0 += __shfl_down_sync(0xffffffffu, p0, 4);
            p1 += __shfl_down_sync(0xffffffffu, p1, 4);
            if (lane == 0) {
                sh_red[p ^ 1][warp * 2 + 0] = p0;
                sh_red[p ^ 1][warp * 2 + 1] = p1;
            }
        }

        // activate OWN gate, then gather activated values of feature g
        float act = (q == 2) ? tanh_fast(z) : sigf(z);
        int lb = lane & ~3;
        float ai = __shfl_sync(0xffffffffu, act, lb + 0);
        float af = __shfl_sync(0xffffffffu, act, lb + 1);
        float ag = __shfl_sync(0xffffffffu, act, lb + 2);
        float ao = __shfl_sync(0xffffffffu, act, lb + 3);

        c = af * c + ai * ag;
        float h = ao * tanh_fast(c);
        hprev = h;
        if (q == 0) sh_h[p ^ 1][g] = h;
        __syncthreads();
    }

    // final logit t=255: reduced at u=256 into buffer 1
    if (tid == 0) {
        float l0 = ba0, l1 = ba1;
        #pragma unroll
        for (int w = 0; w < 8; w++) {
            l0 += sh_red[1][2 * w];
            l1 += sh_red[1][2 * w + 1];
        }
        int tok = sh_tok[LL - 1];
        float m = fmaxf(l0, l1);
        float lse = m + __logf(__expf(l0 - m) + __expf(l1 - m));
        lpsum += (tok ? l1 : l0) - lse;
        out[b] = lpsum;
    }
}

// ---------------------------------------------------------------------------
// Launch. Input order:
// 0:s 1:g 2:W_emb 3:b_emb 4:W_g1 5:b_g1 6:W_g2 7:b_g2 8:W_gh 9:b_gh
// 10:W_gc 11:b_gc 12:Wi 13:Wh 14:b_lstm 15:W_amp 16:b_amp
// ---------------------------------------------------------------------------
extern "C" void kernel_launch(void* const* d_in, const int* in_sizes, int n_in,
                              void* d_out, int out_size) {
    const int*   s      = (const int*)  d_in[0];
    const float* g      = (const float*)d_in[1];
    const float* W_emb  = (const float*)d_in[2];
    const float* b_emb  = (const float*)d_in[3];
    const float* W_g1   = (const float*)d_in[4];
    const float* b_g1   = (const float*)d_in[5];
    const float* W_g2   = (const float*)d_in[6];
    const float* b_g2   = (const float*)d_in[7];
    const float* W_gh   = (const float*)d_in[8];
    const float* b_gh   = (const float*)d_in[9];
    const float* W_gc   = (const float*)d_in[10];
    const float* b_gc   = (const float*)d_in[11];
    const float* Wi     = (const float*)d_in[12];
    const float* Wh     = (const float*)d_in[13];
    const float* b_lstm = (const float*)d_in[14];
    const float* W_amp  = (const float*)d_in[15];
    const float* b_amp  = (const float*)d_in[16];
    float* out = (float*)d_out;

    precompute_kernel<<<BB, 256>>>(g, W_emb, b_emb, W_g1, b_g1, W_g2, b_g2,
                                   W_gh, b_gh, W_gc, b_gc, Wi, b_lstm);
    lstm_kernel<<<BB, 256>>>(s, Wh, W_amp, b_amp, out);
}

// round 6
// speedup vs baseline: 1.1694x; 1.1338x over previous
#include <cuda_runtime.h>

#define BB 2048
#define LL 256
#define FF 64
#define HH 32
#define G4 256   // 4*F

// Scratch (device globals; no allocation allowed)
__device__ float d_A[BB * G4];     // per-batch input bias: (b_emb+g_vec[b])@Wi + b_lstm
__device__ float d_E[2 * G4];      // per-token embedding projection: W_emb[k]@Wi
__device__ float d_h0[BB * FF];
__device__ float d_c0[BB * FF];

typedef unsigned long long u64;

__device__ __forceinline__ u64 pack2(float lo, float hi) {
    u64 r; asm("mov.b64 %0, {%1,%2};" : "=l"(r) : "f"(lo), "f"(hi)); return r;
}
__device__ __forceinline__ void fma2(u64 &d, u64 a, u64 b) {
    asm("fma.rn.f32x2 %0, %1, %2, %0;" : "+l"(d) : "l"(a), "l"(b));
}
__device__ __forceinline__ u64 add2(u64 a, u64 b) {
    u64 r; asm("add.rn.f32x2 %0, %1, %2;" : "=l"(r) : "l"(a), "l"(b)); return r;
}
__device__ __forceinline__ float sum2(u64 v) {
    float lo, hi; asm("mov.b64 {%0,%1}, %2;" : "=f"(lo), "=f"(hi) : "l"(v));
    return lo + hi;
}
// Fast gates validated at rel_err 2.5e-7
__device__ __forceinline__ float sigf(float x) {
    return __fdividef(1.f, 1.f + __expf(-x));
}
__device__ __forceinline__ float tanh_fast(float x) {
    return __fdividef(2.f, 1.f + __expf(-2.f * x)) - 1.f;
}

// ---------------------------------------------------------------------------
// Kernel 1: precompute A[b], E[k], h0[b], c0[b]   (proven)
// ---------------------------------------------------------------------------
__global__ void precompute_kernel(
    const float* __restrict__ g,
    const float* __restrict__ W_emb,  const float* __restrict__ b_emb,
    const float* __restrict__ W_g1,   const float* __restrict__ b_g1,
    const float* __restrict__ W_g2,   const float* __restrict__ b_g2,
    const float* __restrict__ W_gh,   const float* __restrict__ b_gh,
    const float* __restrict__ W_gc,   const float* __restrict__ b_gc,
    const float* __restrict__ Wi,     const float* __restrict__ b_lstm)
{
    int b = blockIdx.x;
    int j = threadIdx.x;
    __shared__ float sh_t[HH];
    __shared__ float sh_gv[FF];

    float gb = g[b];
    if (j < HH) sh_t[j] = tanhf(gb * W_g1[j] + b_g1[j]);
    __syncthreads();
    if (j < FF) {
        float acc = b_g2[j];
        #pragma unroll 8
        for (int h = 0; h < HH; h++) acc += sh_t[h] * W_g2[h * FF + j];
        sh_gv[j] = acc;
        d_h0[b * FF + j] = gb * W_gh[j] + b_gh[j];
        d_c0[b * FF + j] = gb * W_gc[j] + b_gc[j];
    }
    __syncthreads();
    float acc = b_lstm[j];
    #pragma unroll 8
    for (int f = 0; f < FF; f++) acc += (b_emb[f] + sh_gv[f]) * Wi[f * G4 + j];
    d_A[b * G4 + j] = acc;

    if (b == 0) {
        float e0 = 0.f, e1 = 0.f;
        #pragma unroll 8
        for (int f = 0; f < FF; f++) {
            float wi = Wi[f * G4 + j];
            e0 += W_emb[f] * wi;
            e1 += W_emb[FF + f] * wi;
        }
        d_E[j] = e0;
        d_E[G4 + j] = e1;
    }
}

// ---------------------------------------------------------------------------
// Kernel 2: LSTM recurrence, G=2 batches per CTA (weight registers amortized,
// every latency link has an independent twin for ILP). Proven R5 dataflow per
// batch: col = (tid&3)*64 + tid/4, one barrier/step, own-gate activation +
// shfl gather, register c, double-buffered h, 2-step deferred logit pipeline.
// Batch0 logits consumed by thread 0 (warp 0), batch1 by thread 32 (warp 1).
// ---------------------------------------------------------------------------
__global__ void __launch_bounds__(256, 2) lstm_kernel(
    const int*   __restrict__ s,      // (B, L)
    const float* __restrict__ Wh,     // (64, 256)
    const float* __restrict__ W_amp,  // (64, 2)
    const float* __restrict__ b_amp,  // (2)
    float* __restrict__ out)          // (B,)
{
    int b0   = 2 * blockIdx.x;
    int b1   = b0 + 1;
    int tid  = threadIdx.x;
    int g    = tid >> 2;        // feature 0..63
    int q    = tid & 3;         // gate 0..3 (i,f,g,o)
    int col  = q * FF + g;      // gate column in [0,256)
    int lane = tid & 31;
    int warp = tid >> 5;

    __shared__ __align__(16) float sh_h[2][2][FF];   // [batch][parity][feat]
    __shared__ int   sh_tok[2][LL];
    __shared__ float sh_red[2][2][16];               // [batch][parity][slot]

    // Wh column `col` (shared by both batches), packed f32x2
    u64 w2[32];
    #pragma unroll
    for (int k = 0; k < 32; k++)
        w2[k] = pack2(Wh[(2 * k) * G4 + col], Wh[(2 * k + 1) * G4 + col]);

    float e0 = d_E[col];
    float ed = d_E[G4 + col] - e0;
    float xbase0  = d_A[b0 * G4 + col] + e0;
    float xbase1  = d_A[b1 * G4 + col] + e0;

    sh_tok[0][tid] = s[b0 * LL + tid];
    sh_tok[1][tid] = s[b1 * LL + tid];
    if (tid < FF) {
        sh_h[0][0][tid] = d_h0[b0 * FF + tid];
        sh_h[1][0][tid] = d_h0[b1 * FF + tid];
    }
    float c0 = d_c0[b0 * FF + g];
    float c1 = d_c0[b1 * FF + g];
    float wa0 = W_amp[g * 2 + 0];
    float wa1 = W_amp[g * 2 + 1];
    float ba0 = b_amp[0], ba1 = b_amp[1];
    float lpsum = 0.f;                 // meaningful in threads 0 and 32 only
    float hprev0 = 0.f, hprev1 = 0.f;
    __syncthreads();

    #pragma unroll 1
    for (int u = 0; u <= LL; u++) {
        int p = u & 1;

        // consume logits for token (u-2): thread 0 -> batch0, thread 32 -> batch1
        if (u >= 2 && (tid == 0 || tid == 32)) {
            int bb = warp;             // 0 or 1
            float l0 = ba0, l1 = ba1;
            #pragma unroll
            for (int w = 0; w < 8; w++) {
                l0 += sh_red[bb][p][2 * w];
                l1 += sh_red[bb][p][2 * w + 1];
            }
            int tok = sh_tok[bb][u - 2];
            float m = fmaxf(l0, l1);
            float lse = m + __logf(__expf(l0 - m) + __expf(l1 - m));
            lpsum += (tok ? l1 : l0) - lse;
        }

        // matvecs for both batches, interleaved (independent FMA chains)
        int t0 = (u == 0) ? 0 : sh_tok[0][u - 1];
        int t1 = (u == 0) ? 0 : sh_tok[1][u - 1];
        float x0 = t0 ? (xbase0 + ed) : xbase0;
        float x1 = t1 ? (xbase1 + ed) : xbase1;
        const ulonglong2* hA = (const ulonglong2*)sh_h[0][p];
        const ulonglong2* hB = (const ulonglong2*)sh_h[1][p];
        u64 a0 = pack2(x0, 0.f), a1 = 0ull;
        u64 d0 = pack2(x1, 0.f), d1 = 0ull;
        #pragma unroll
        for (int i = 0; i < 8; i++) {
            ulonglong2 ha = hA[2 * i];
            ulonglong2 hb = hA[2 * i + 1];
            ulonglong2 ga = hB[2 * i];
            ulonglong2 gb = hB[2 * i + 1];
            fma2(a0, ha.x, w2[4 * i + 0]);
            fma2(d0, ga.x, w2[4 * i + 0]);
            fma2(a1, ha.y, w2[4 * i + 1]);
            fma2(d1, ga.y, w2[4 * i + 1]);
            fma2(a0, hb.x, w2[4 * i + 2]);
            fma2(d0, gb.x, w2[4 * i + 2]);
            fma2(a1, hb.y, w2[4 * i + 3]);
            fma2(d1, gb.y, w2[4 * i + 3]);
        }
        float z0 = sum2(add2(a0, a1));
        float z1 = sum2(add2(d0, d1));

        // deferred logit partials for h(u-1), both batches (independent work
        // that fills matvec stalls). Same-q shfl trees; lane 0 stores.
        if (u >= 1) {
            float p00 = hprev0 * wa0, p01 = hprev0 * wa1;
            float p10 = hprev1 * wa0, p11 = hprev1 * wa1;
            #pragma unroll
            for (int o = 16; o >= 4; o >>= 1) {
                p00 += __shfl_down_sync(0xffffffffu, p00, o);
                p01 += __shfl_down_sync(0xffffffffu, p01, o);
                p10 += __shfl_down_sync(0xffffffffu, p10, o);
                p11 += __shfl_down_sync(0xffffffffu, p11, o);
            }
            if (lane == 0) {
                sh_red[0][p ^ 1][warp * 2 + 0] = p00;
                sh_red[0][p ^ 1][warp * 2 + 1] = p01;
                sh_red[1][p ^ 1][warp * 2 + 0] = p10;
                sh_red[1][p ^ 1][warp * 2 + 1] = p11;
            }
        }

        // activate OWN gate (both batches), gather activated 4-tuples
        float act0 = (q == 2) ? tanh_fast(z0) : sigf(z0);
        float act1 = (q == 2) ? tanh_fast(z1) : sigf(z1);
        int lb = lane & ~3;
        float ai0 = __shfl_sync(0xffffffffu, act0, lb + 0);
        float ai1 = __shfl_sync(0xffffffffu, act1, lb + 0);
        float af0 = __shfl_sync(0xffffffffu, act0, lb + 1);
        float af1 = __shfl_sync(0xffffffffu, act1, lb + 1);
        float ag0 = __shfl_sync(0xffffffffu, act0, lb + 2);
        float ag1 = __shfl_sync(0xffffffffu, act1, lb + 2);
        float ao0 = __shfl_sync(0xffffffffu, act0, lb + 3);
        float ao1 = __shfl_sync(0xffffffffu, act1, lb + 3);

        c0 = af0 * c0 + ai0 * ag0;
        c1 = af1 * c1 + ai1 * ag1;
        float h0 = ao0 * tanh_fast(c0);
        float h1 = ao1 * tanh_fast(c1);
        hprev0 = h0;
        hprev1 = h1;
        if (q == 0) {
            sh_h[0][p ^ 1][g] = h0;
            sh_h[1][p ^ 1][g] = h1;
        }
        __syncthreads();
    }

    // final logit t=255 (reduced at u=256 into parity buffer 1)
    if (tid == 0 || tid == 32) {
        int bb = warp;
        float l0 = ba0, l1 = ba1;
        #pragma unroll
        for (int w = 0; w < 8; w++) {
            l0 += sh_red[bb][1][2 * w];
            l1 += sh_red[bb][1][2 * w + 1];
        }
        int tok = sh_tok[bb][LL - 1];
        float m = fmaxf(l0, l1);
        float lse = m + __logf(__expf(l0 - m) + __expf(l1 - m));
        lpsum += (tok ? l1 : l0) - lse;
        out[bb ? b1 : b0] = lpsum;
    }
}

// ---------------------------------------------------------------------------
// Launch. Input order:
// 0:s 1:g 2:W_emb 3:b_emb 4:W_g1 5:b_g1 6:W_g2 7:b_g2 8:W_gh 9:b_gh
// 10:W_gc 11:b_gc 12:Wi 13:Wh 14:b_lstm 15:W_amp 16:b_amp
// ---------------------------------------------------------------------------
extern "C" void kernel_launch(void* const* d_in, const int* in_sizes, int n_in,
                              void* d_out, int out_size) {
    const int*   s      = (const int*)  d_in[0];
    const float* g      = (const float*)d_in[1];
    const float* W_emb  = (const float*)d_in[2];
    const float* b_emb  = (const float*)d_in[3];
    const float* W_g1   = (const float*)d_in[4];
    const float* b_g1   = (const float*)d_in[5];
    const float* W_g2   = (const float*)d_in[6];
    const float* b_g2   = (const float*)d_in[7];
    const float* W_gh   = (const float*)d_in[8];
    const float* b_gh   = (const float*)d_in[9];
    const float* W_gc   = (const float*)d_in[10];
    const float* b_gc   = (const float*)d_in[11];
    const float* Wi     = (const float*)d_in[12];
    const float* Wh     = (const float*)d_in[13];
    const float* b_lstm = (const float*)d_in[14];
    const float* W_amp  = (const float*)d_in[15];
    const float* b_amp  = (const float*)d_in[16];
    float* out = (float*)d_out;

    precompute_kernel<<<BB, 256>>>(g, W_emb, b_emb, W_g1, b_g1, W_g2, b_g2,
                                   W_gh, b_gh, W_gc, b_gc, Wi, b_lstm);
    lstm_kernel<<<BB / 2, 256>>>(s, Wh, W_amp, b_amp, out);
}